// round 2
// baseline (speedup 1.0000x reference)
#include <cuda_runtime.h>
#include <cstdint>

#define N_NODES 8192
#define C 256
#define NWORDS 256   // 8192 bits / 32 per row

// Scratch (device globals — no allocation allowed)
__device__ unsigned g_bitmap[N_NODES * NWORDS];   // 8 MiB adjacency bitmap
__device__ float    g_xs[N_NODES * C];            // dis[j] * x[j]
__device__ float    g_dis[N_NODES];
__device__ float    g_pre[N_NODES * C];           // norm @ x

// ---------------------------------------------------------------- K1: clear
__global__ void k_zero_bitmap() {
    int i = blockIdx.x * blockDim.x + threadIdx.x;
    g_bitmap[i] = 0u;
}

// ---------------------------------------------------------------- K2: edges
// edge_index is int32 (harness dtype set: float32/int32/bf16; JAX x64-off
// downcasts the declared int64). Layout (2, E) row-major.
__global__ void k_set_edges(const int* __restrict__ ei, int E) {
    int e = blockIdx.x * blockDim.x + threadIdx.x;
    if (e < E) {
        int r = ei[e]     & (N_NODES - 1);   // mask = crash insurance only
        int c = ei[E + e] & (N_NODES - 1);
        atomicOr(&g_bitmap[r * NWORDS + (c >> 5)], 1u << (c & 31));
    }
}

// ------------------------------------------------- K3: degree + scale rows
// One block per row. deg = popcount(row bits) + 1 (the +I). dis = rsqrt(deg).
// Writes xs[i] = dis[i] * x[i]. (If a self-loop bit exists, adj[i][i]=2 in the
// reference; popcount counts it once and +1 adds the eye -> deg matches, and
// the SpMM eye-term handling below matches too.)
__global__ void k_deg_scale(const float* __restrict__ x) {
    int i = blockIdx.x;
    int t = threadIdx.x;   // 0..255 (= word index = channel index)
    __shared__ int red[256];
    __shared__ float sdis;
    red[t] = __popc(g_bitmap[i * NWORDS + t]);
    __syncthreads();
    #pragma unroll
    for (int s = 128; s > 0; s >>= 1) {
        if (t < s) red[t] += red[t + s];
        __syncthreads();
    }
    if (t == 0) {
        float d = (float)(red[0] + 1);   // always >= 1
        float v = rsqrtf(d);
        sdis = v;
        g_dis[i] = v;
    }
    __syncthreads();
    g_xs[i * C + t] = sdis * x[i * C + t];
}

// --------------------------------------------------------------- K4: SpMM
// pre[i] = dis[i] * ( sum_{j in bits(i)} dis[j]*x[j]  +  dis[i]*x[i] )
// One block per row; 256 threads = 256 channels. Uniform bitmap scan;
// every set bit = one coalesced 1KB row gather (L2-resident working set).
__global__ void k_spmm() {
    int i = blockIdx.x;
    int t = threadIdx.x;
    __shared__ unsigned words[NWORDS];
    words[t] = g_bitmap[i * NWORDS + t];
    float acc = g_xs[i * C + t];          // eye contribution: + dis[i]*x[i]
    __syncthreads();
    float disI = g_dis[i];
    #pragma unroll 4
    for (int w = 0; w < NWORDS; w++) {
        unsigned word = words[w];
        while (word) {
            int b = __ffs(word) - 1;
            word &= word - 1;
            int j = (w << 5) + b;
            acc += g_xs[j * C + t];
        }
    }
    g_pre[i * C + t] = disI * acc;
}

// --------------------------------------------------------------- K5: GEMM
// out[8192, 256] = pre @ W^T + b1 + b2.  W is (out,in) row-major, so both
// operands are K-contiguous: out = A * B^T.
#define BM 64
#define BN 64
#define BK 16
__global__ __launch_bounds__(256) void k_gemm(
    const float* __restrict__ Wm,
    const float* __restrict__ b1,
    const float* __restrict__ b2,
    float* __restrict__ out)
{
    __shared__ float As[BK][BM];
    __shared__ float Bs[BK][BN];
    int tid = threadIdx.x;
    int tx = tid & 15;        // 0..15  -> 4 output cols each
    int ty = tid >> 4;        // 0..15  -> 4 output rows each
    int lr = tid >> 2;        // 0..63  load row within tile
    int lq = tid & 3;         // 0..3   float4 slot within BK
    int row0 = blockIdx.x * BM;
    int col0 = blockIdx.y * BN;

    float acc[4][4] = {};
    for (int k0 = 0; k0 < C; k0 += BK) {
        float4 a = *(const float4*)&g_pre[(row0 + lr) * C + k0 + lq * 4];
        float4 b = *(const float4*)&Wm[(col0 + lr) * C + k0 + lq * 4];
        As[lq * 4 + 0][lr] = a.x; As[lq * 4 + 1][lr] = a.y;
        As[lq * 4 + 2][lr] = a.z; As[lq * 4 + 3][lr] = a.w;
        Bs[lq * 4 + 0][lr] = b.x; Bs[lq * 4 + 1][lr] = b.y;
        Bs[lq * 4 + 2][lr] = b.z; Bs[lq * 4 + 3][lr] = b.w;
        __syncthreads();
        #pragma unroll
        for (int kk = 0; kk < BK; kk++) {
            float4 av = *(const float4*)&As[kk][ty * 4];
            float4 bv = *(const float4*)&Bs[kk][tx * 4];
            float ar[4] = {av.x, av.y, av.z, av.w};
            float br[4] = {bv.x, bv.y, bv.z, bv.w};
            #pragma unroll
            for (int ii = 0; ii < 4; ii++)
                #pragma unroll
                for (int jj = 0; jj < 4; jj++)
                    acc[ii][jj] += ar[ii] * br[jj];
        }
        __syncthreads();
    }
    #pragma unroll
    for (int ii = 0; ii < 4; ii++) {
        int r = row0 + ty * 4 + ii;
        #pragma unroll
        for (int jj = 0; jj < 4; jj++) {
            int c = col0 + tx * 4 + jj;
            out[r * C + c] = acc[ii][jj] + b1[c] + b2[c];
        }
    }
}

// ---------------------------------------------------------------- launch
// Inputs resolved BY ELEMENT COUNT (robust to metadata ordering):
//   2097152 -> x, 65536 -> W, 262144 -> edge_index, 256 (x2) -> biases.
extern "C" void kernel_launch(void* const* d_in, const int* in_sizes, int n_in,
                              void* d_out, int out_size)
{
    const float* x  = nullptr;
    const float* Wm = nullptr;
    const int*   ei = nullptr;
    const float* b1 = nullptr;
    const float* b2 = nullptr;

    for (int i = 0; i < n_in; i++) {
        int s = in_sizes[i];
        if (s == N_NODES * C)        x  = (const float*)d_in[i];
        else if (s == C * C)         Wm = (const float*)d_in[i];
        else if (s == 2 * 131072)    ei = (const int*)d_in[i];
        else if (s == C) {
            if (!b1) b1 = (const float*)d_in[i];
            else     b2 = (const float*)d_in[i];
        }
    }
    if (!b2) b2 = b1;   // defensive; shouldn't happen
    float* out = (float*)d_out;
    int E = 131072;

    k_zero_bitmap<<<(N_NODES * NWORDS) / 256, 256>>>();
    k_set_edges<<<(E + 255) / 256, 256>>>(ei, E);
    k_deg_scale<<<N_NODES, 256>>>(x);
    k_spmm<<<N_NODES, 256>>>();
    k_gemm<<<dim3(N_NODES / BM, C / BN), 256>>>(Wm, b1, b2, out);
}

// round 3
// speedup vs baseline: 1.7521x; 1.7521x over previous
#include <cuda_runtime.h>
#include <cstdint>

#define N_NODES 8192
#define C 256
#define NWORDS 256   // 8192 bits / 32 per row
#define MAXDEG 128   // Poisson(16); P(deg>100) astronomically small
#define ROWS_PER_BLK 8

// Scratch (device globals — no allocation allowed)
__device__ unsigned g_bitmap[N_NODES * NWORDS];   // 8 MiB adjacency bitmap
__device__ float    g_xs[N_NODES * C];            // dis[j] * x[j]
__device__ float    g_dis[N_NODES];
__device__ float    g_pre[N_NODES * C];           // norm @ x

// ---------------------------------------------------------------- K1: clear
__global__ void k_zero_bitmap() {
    int i = blockIdx.x * blockDim.x + threadIdx.x;
    g_bitmap[i] = 0u;
}

// ---------------------------------------------------------------- K2: edges
__global__ void k_set_edges(const int* __restrict__ ei, int E) {
    int e = blockIdx.x * blockDim.x + threadIdx.x;
    if (e < E) {
        int r = ei[e]     & (N_NODES - 1);
        int c = ei[E + e] & (N_NODES - 1);
        atomicOr(&g_bitmap[r * NWORDS + (c >> 5)], 1u << (c & 31));
    }
}

// ------------------------------------------------- K3: degree + scale rows
__global__ void k_deg_scale(const float* __restrict__ x) {
    int i = blockIdx.x;
    int t = threadIdx.x;   // 0..255
    __shared__ int red[256];
    __shared__ float sdis;
    red[t] = __popc(g_bitmap[i * NWORDS + t]);
    __syncthreads();
    #pragma unroll
    for (int s = 128; s > 0; s >>= 1) {
        if (t < s) red[t] += red[t + s];
        __syncthreads();
    }
    if (t == 0) {
        float d = (float)(red[0] + 1);   // + eye; always >= 1
        float v = rsqrtf(d);
        sdis = v;
        g_dis[i] = v;
    }
    __syncthreads();
    g_xs[i * C + t] = sdis * x[i * C + t];
}

// --------------------------------------------------------------- K4: SpMM
// One WARP per row; 8 rows per 256-thread block.
// Phase 1: decode bitmap once per row (popc + warp prefix scan -> smem list).
// Phase 2: each lane owns 8 channels; gather neighbor rows with LDG.128 pairs.
__global__ __launch_bounds__(256) void k_spmm() {
    int warp = threadIdx.x >> 5;
    int lane = threadIdx.x & 31;
    int row  = blockIdx.x * ROWS_PER_BLK + warp;

    __shared__ int s_idx[ROWS_PER_BLK][MAXDEG];

    // ---- decode: each lane scans 8 words ----
    const unsigned* bm = &g_bitmap[row * NWORDS];
    unsigned w[8];
    *(uint4*)&w[0] = *(const uint4*)&bm[lane * 8];
    *(uint4*)&w[4] = *(const uint4*)&bm[lane * 8 + 4];
    int cnt = 0;
    #pragma unroll
    for (int q = 0; q < 8; q++) cnt += __popc(w[q]);
    // inclusive warp scan -> exclusive offset
    int off = cnt;
    #pragma unroll
    for (int d = 1; d < 32; d <<= 1) {
        int v = __shfl_up_sync(0xFFFFFFFFu, off, d);
        if (lane >= d) off += v;
    }
    int total = __shfl_sync(0xFFFFFFFFu, off, 31);
    off -= cnt;
    if (total > MAXDEG) total = MAXDEG;          // safety clamp (never hits)
    int p = off;
    #pragma unroll
    for (int q = 0; q < 8; q++) {
        unsigned word = w[q];
        while (word) {
            int b = __ffs(word) - 1;
            word &= word - 1;
            if (p < MAXDEG) s_idx[warp][p] = ((lane * 8 + q) << 5) + b;
            p++;
        }
    }
    __syncwarp();

    // ---- accumulate: lane handles channels [lane*8, lane*8+8) ----
    const float* xs = g_xs;
    int ch = lane * 8;
    float4 a0 = *(const float4*)(xs + row * C + ch);      // eye term
    float4 a1 = *(const float4*)(xs + row * C + ch + 4);

    int k = 0;
    for (; k + 4 <= total; k += 4) {
        int4 j4 = *(const int4*)&s_idx[warp][k];
        const float* p0 = xs + j4.x * C + ch;
        const float* p1 = xs + j4.y * C + ch;
        const float* p2 = xs + j4.z * C + ch;
        const float* p3 = xs + j4.w * C + ch;
        float4 v00 = *(const float4*)p0;
        float4 v01 = *(const float4*)(p0 + 4);
        float4 v10 = *(const float4*)p1;
        float4 v11 = *(const float4*)(p1 + 4);
        float4 v20 = *(const float4*)p2;
        float4 v21 = *(const float4*)(p2 + 4);
        float4 v30 = *(const float4*)p3;
        float4 v31 = *(const float4*)(p3 + 4);
        a0.x += v00.x; a0.y += v00.y; a0.z += v00.z; a0.w += v00.w;
        a1.x += v01.x; a1.y += v01.y; a1.z += v01.z; a1.w += v01.w;
        a0.x += v10.x; a0.y += v10.y; a0.z += v10.z; a0.w += v10.w;
        a1.x += v11.x; a1.y += v11.y; a1.z += v11.z; a1.w += v11.w;
        a0.x += v20.x; a0.y += v20.y; a0.z += v20.z; a0.w += v20.w;
        a1.x += v21.x; a1.y += v21.y; a1.z += v21.z; a1.w += v21.w;
        a0.x += v30.x; a0.y += v30.y; a0.z += v30.z; a0.w += v30.w;
        a1.x += v31.x; a1.y += v31.y; a1.z += v31.z; a1.w += v31.w;
    }
    for (; k < total; k++) {
        int j = s_idx[warp][k];
        float4 v0 = *(const float4*)(xs + j * C + ch);
        float4 v1 = *(const float4*)(xs + j * C + ch + 4);
        a0.x += v0.x; a0.y += v0.y; a0.z += v0.z; a0.w += v0.w;
        a1.x += v1.x; a1.y += v1.y; a1.z += v1.z; a1.w += v1.w;
    }

    float disI = g_dis[row];
    a0.x *= disI; a0.y *= disI; a0.z *= disI; a0.w *= disI;
    a1.x *= disI; a1.y *= disI; a1.z *= disI; a1.w *= disI;
    *(float4*)(g_pre + row * C + ch)     = a0;
    *(float4*)(g_pre + row * C + ch + 4) = a1;
}

// --------------------------------------------------------------- K5: GEMM
// out[8192, 256] = pre @ W^T + b1 + b2 (both operands K-contiguous).
#define BM 64
#define BN 64
#define BK 16
__global__ __launch_bounds__(256) void k_gemm(
    const float* __restrict__ Wm,
    const float* __restrict__ b1,
    const float* __restrict__ b2,
    float* __restrict__ out)
{
    __shared__ float As[BK][BM];
    __shared__ float Bs[BK][BN];
    int tid = threadIdx.x;
    int tx = tid & 15;
    int ty = tid >> 4;
    int lr = tid >> 2;
    int lq = tid & 3;
    int row0 = blockIdx.x * BM;
    int col0 = blockIdx.y * BN;

    float acc[4][4] = {};
    for (int k0 = 0; k0 < C; k0 += BK) {
        float4 a = *(const float4*)&g_pre[(row0 + lr) * C + k0 + lq * 4];
        float4 b = *(const float4*)&Wm[(col0 + lr) * C + k0 + lq * 4];
        As[lq * 4 + 0][lr] = a.x; As[lq * 4 + 1][lr] = a.y;
        As[lq * 4 + 2][lr] = a.z; As[lq * 4 + 3][lr] = a.w;
        Bs[lq * 4 + 0][lr] = b.x; Bs[lq * 4 + 1][lr] = b.y;
        Bs[lq * 4 + 2][lr] = b.z; Bs[lq * 4 + 3][lr] = b.w;
        __syncthreads();
        #pragma unroll
        for (int kk = 0; kk < BK; kk++) {
            float4 av = *(const float4*)&As[kk][ty * 4];
            float4 bv = *(const float4*)&Bs[kk][tx * 4];
            float ar[4] = {av.x, av.y, av.z, av.w};
            float br[4] = {bv.x, bv.y, bv.z, bv.w};
            #pragma unroll
            for (int ii = 0; ii < 4; ii++)
                #pragma unroll
                for (int jj = 0; jj < 4; jj++)
                    acc[ii][jj] += ar[ii] * br[jj];
        }
        __syncthreads();
    }
    #pragma unroll
    for (int ii = 0; ii < 4; ii++) {
        int r = row0 + ty * 4 + ii;
        #pragma unroll
        for (int jj = 0; jj < 4; jj++) {
            int c = col0 + tx * 4 + jj;
            out[r * C + c] = acc[ii][jj] + b1[c] + b2[c];
        }
    }
}

// ---------------------------------------------------------------- launch
extern "C" void kernel_launch(void* const* d_in, const int* in_sizes, int n_in,
                              void* d_out, int out_size)
{
    const float* x  = nullptr;
    const float* Wm = nullptr;
    const int*   ei = nullptr;
    const float* b1 = nullptr;
    const float* b2 = nullptr;

    for (int i = 0; i < n_in; i++) {
        int s = in_sizes[i];
        if (s == N_NODES * C)        x  = (const float*)d_in[i];
        else if (s == C * C)         Wm = (const float*)d_in[i];
        else if (s == 2 * 131072)    ei = (const int*)d_in[i];
        else if (s == C) {
            if (!b1) b1 = (const float*)d_in[i];
            else     b2 = (const float*)d_in[i];
        }
    }
    if (!b2) b2 = b1;
    float* out = (float*)d_out;
    int E = 131072;

    k_zero_bitmap<<<(N_NODES * NWORDS) / 256, 256>>>();
    k_set_edges<<<(E + 255) / 256, 256>>>(ei, E);
    k_deg_scale<<<N_NODES, 256>>>(x);
    k_spmm<<<N_NODES / ROWS_PER_BLK, 256>>>();
    k_gemm<<<dim3(N_NODES / BM, C / BN), 256>>>(Wm, b1, b2, out);
}

// round 5
// speedup vs baseline: 2.0535x; 1.1720x over previous
#include <cuda_runtime.h>
#include <cstdint>

#define N_NODES 8192
#define C 256
#define NWORDS 256   // 8192 bits / 32 per row
#define MAXDEG 128
#define ROWS_PER_BLK 8

// Scratch (device globals — no allocation allowed)
__device__ unsigned g_bitmap[N_NODES * NWORDS];   // 8 MiB adjacency bitmap
__device__ float    g_dis[N_NODES];
__device__ float    g_pre[N_NODES * C];           // norm @ x

// ---------------------------------------------------------------- K1: clear
__global__ void k_zero_bitmap() {
    int i = blockIdx.x * blockDim.x + threadIdx.x;
    g_bitmap[i] = 0u;
}

// ---------------------------------------------------------------- K2: edges
__global__ void k_set_edges(const int* __restrict__ ei, int E) {
    int e = blockIdx.x * blockDim.x + threadIdx.x;
    if (e < E) {
        int r = ei[e]     & (N_NODES - 1);
        int c = ei[E + e] & (N_NODES - 1);
        atomicOr(&g_bitmap[r * NWORDS + (c >> 5)], 1u << (c & 31));
    }
}

// ------------------------------------------------- K3: degree -> dis only
__global__ __launch_bounds__(256) void k_deg() {
    int warp = threadIdx.x >> 5;
    int lane = threadIdx.x & 31;
    int row  = blockIdx.x * ROWS_PER_BLK + warp;
    const unsigned* bm = &g_bitmap[row * NWORDS];
    uint4 a = *(const uint4*)&bm[lane * 8];
    uint4 b = *(const uint4*)&bm[lane * 8 + 4];
    int cnt = __popc(a.x) + __popc(a.y) + __popc(a.z) + __popc(a.w)
            + __popc(b.x) + __popc(b.y) + __popc(b.z) + __popc(b.w);
    #pragma unroll
    for (int d = 16; d; d >>= 1) cnt += __shfl_xor_sync(0xFFFFFFFFu, cnt, d);
    if (lane == 0) g_dis[row] = rsqrtf((float)(cnt + 1));
}

// --------------------------------------------------------------- K4: SpMM
// pre[i] = dis_i * ( dis_i*x_i + sum_{j in bits(i)} dis_j*x_j )
__global__ __launch_bounds__(256) void k_spmm(const float* __restrict__ x) {
    int warp = threadIdx.x >> 5;
    int lane = threadIdx.x & 31;
    int row  = blockIdx.x * ROWS_PER_BLK + warp;

    __shared__ int s_idx[ROWS_PER_BLK][MAXDEG];

    const unsigned* bm = &g_bitmap[row * NWORDS];
    unsigned w[8];
    *(uint4*)&w[0] = *(const uint4*)&bm[lane * 8];
    *(uint4*)&w[4] = *(const uint4*)&bm[lane * 8 + 4];
    int cnt = 0;
    #pragma unroll
    for (int q = 0; q < 8; q++) cnt += __popc(w[q]);
    int off = cnt;
    #pragma unroll
    for (int d = 1; d < 32; d <<= 1) {
        int v = __shfl_up_sync(0xFFFFFFFFu, off, d);
        if (lane >= d) off += v;
    }
    int total = __shfl_sync(0xFFFFFFFFu, off, 31);
    off -= cnt;
    if (total > MAXDEG) total = MAXDEG;
    int p = off;
    #pragma unroll
    for (int q = 0; q < 8; q++) {
        unsigned word = w[q];
        while (word) {
            int b = __ffs(word) - 1;
            word &= word - 1;
            if (p < MAXDEG) s_idx[warp][p] = ((lane * 8 + q) << 5) + b;
            p++;
        }
    }
    __syncwarp();

    int ch = lane * 8;
    float disI = g_dis[row];
    float4 a0 = *(const float4*)(x + row * C + ch);
    float4 a1 = *(const float4*)(x + row * C + ch + 4);
    a0.x *= disI; a0.y *= disI; a0.z *= disI; a0.w *= disI;   // eye: dis_i*x_i
    a1.x *= disI; a1.y *= disI; a1.z *= disI; a1.w *= disI;

    int k = 0;
    for (; k + 4 <= total; k += 4) {
        int4 j4 = *(const int4*)&s_idx[warp][k];
        float d0 = g_dis[j4.x], d1 = g_dis[j4.y], d2 = g_dis[j4.z], d3 = g_dis[j4.w];
        const float* p0 = x + j4.x * C + ch;
        const float* p1 = x + j4.y * C + ch;
        const float* p2 = x + j4.z * C + ch;
        const float* p3 = x + j4.w * C + ch;
        float4 v00 = *(const float4*)p0, v01 = *(const float4*)(p0 + 4);
        float4 v10 = *(const float4*)p1, v11 = *(const float4*)(p1 + 4);
        float4 v20 = *(const float4*)p2, v21 = *(const float4*)(p2 + 4);
        float4 v30 = *(const float4*)p3, v31 = *(const float4*)(p3 + 4);
        a0.x += d0*v00.x; a0.y += d0*v00.y; a0.z += d0*v00.z; a0.w += d0*v00.w;
        a1.x += d0*v01.x; a1.y += d0*v01.y; a1.z += d0*v01.z; a1.w += d0*v01.w;
        a0.x += d1*v10.x; a0.y += d1*v10.y; a0.z += d1*v10.z; a0.w += d1*v10.w;
        a1.x += d1*v11.x; a1.y += d1*v11.y; a1.z += d1*v11.z; a1.w += d1*v11.w;
        a0.x += d2*v20.x; a0.y += d2*v20.y; a0.z += d2*v20.z; a0.w += d2*v20.w;
        a1.x += d2*v21.x; a1.y += d2*v21.y; a1.z += d2*v21.z; a1.w += d2*v21.w;
        a0.x += d3*v30.x; a0.y += d3*v30.y; a0.z += d3*v30.z; a0.w += d3*v30.w;
        a1.x += d3*v31.x; a1.y += d3*v31.y; a1.z += d3*v31.z; a1.w += d3*v31.w;
    }
    for (; k < total; k++) {
        int j = s_idx[warp][k];
        float dj = g_dis[j];
        float4 v0 = *(const float4*)(x + j * C + ch);
        float4 v1 = *(const float4*)(x + j * C + ch + 4);
        a0.x += dj*v0.x; a0.y += dj*v0.y; a0.z += dj*v0.z; a0.w += dj*v0.w;
        a1.x += dj*v1.x; a1.y += dj*v1.y; a1.z += dj*v1.z; a1.w += dj*v1.w;
    }

    a0.x *= disI; a0.y *= disI; a0.z *= disI; a0.w *= disI;
    a1.x *= disI; a1.y *= disI; a1.z *= disI; a1.w *= disI;
    *(float4*)(g_pre + row * C + ch)     = a0;
    *(float4*)(g_pre + row * C + ch + 4) = a1;
}

// ------------------------------------------- K5: tf32 mma.sync GEMM
// out[8192,256] = pre @ W^T + b1 + b2.
// CTA tile 128x128, 8 warps (2x4), warp tile 64x32, K chunk 16, dbl-buffered.
#define GT_M 128
#define GT_N 128
#define KSTEP 16
#define NKC (C / KSTEP)   // 16
#define LDP 20            // padded smem row stride (floats); conflict-free

__device__ __forceinline__ uint32_t f2tf32(float f) {
    uint32_t r;
    asm("cvt.rna.tf32.f32 %0, %1;" : "=r"(r) : "f"(f));
    return r;
}
__device__ __forceinline__ uint4 cvt4(float4 v) {
    uint4 r;
    r.x = f2tf32(v.x); r.y = f2tf32(v.y); r.z = f2tf32(v.z); r.w = f2tf32(v.w);
    return r;
}
__device__ __forceinline__ void mma_tf32(float* c, const uint32_t* a, const uint32_t* b) {
    asm volatile(
        "mma.sync.aligned.m16n8k8.row.col.f32.tf32.tf32.f32 "
        "{%0,%1,%2,%3}, {%4,%5,%6,%7}, {%8,%9}, {%0,%1,%2,%3};"
        : "+f"(c[0]), "+f"(c[1]), "+f"(c[2]), "+f"(c[3])
        : "r"(a[0]), "r"(a[1]), "r"(a[2]), "r"(a[3]), "r"(b[0]), "r"(b[1]));
}

__global__ __launch_bounds__(256) void k_gemm_mma(
    const float* __restrict__ Wm,
    const float* __restrict__ b1,
    const float* __restrict__ b2,
    float* __restrict__ out)
{
    __shared__ uint32_t As[2][GT_M * LDP];
    __shared__ uint32_t Bs[2][GT_N * LDP];
    __shared__ float sbias[GT_N];

    int tid  = threadIdx.x;
    int wid  = tid >> 5;
    int lane = tid & 31;
    int wm   = wid >> 2;           // 0..1
    int wn   = wid & 3;            // 0..3
    int row0 = blockIdx.x * GT_M;
    int col0 = blockIdx.y * GT_N;

    if (tid < GT_N) sbias[tid] = b1[col0 + tid] + b2[col0 + tid];

    // gmem load mapping: thread -> (row = tid/2, 8-float half = (tid&1)*8)
    int grow = tid >> 1;
    int gcol = (tid & 1) * 8;
    const float* agm = g_pre + (size_t)(row0 + grow) * C + gcol;
    const float* bgm = Wm    + (size_t)(col0 + grow) * C + gcol;
    uint32_t sw = grow * LDP + gcol;   // smem word offset

    // prologue: chunk 0
    float4 pa0 = *(const float4*)(agm);
    float4 pa1 = *(const float4*)(agm + 4);
    float4 pb0 = *(const float4*)(bgm);
    float4 pb1 = *(const float4*)(bgm + 4);
    *(uint4*)&As[0][sw]     = cvt4(pa0);
    *(uint4*)&As[0][sw + 4] = cvt4(pa1);
    *(uint4*)&Bs[0][sw]     = cvt4(pb0);
    *(uint4*)&Bs[0][sw + 4] = cvt4(pb1);
    __syncthreads();

    float acc[4][4][4] = {};   // [mt][nt][frag]
    int l4  = lane >> 2;       // 0..7
    int lk  = lane & 3;        // 0..3

    for (int kc = 0; kc < NKC; kc++) {
        int st = kc & 1;
        if (kc < NKC - 1) {
            int ko = (kc + 1) * KSTEP;
            pa0 = *(const float4*)(agm + ko);
            pa1 = *(const float4*)(agm + ko + 4);
            pb0 = *(const float4*)(bgm + ko);
            pb1 = *(const float4*)(bgm + ko + 4);
        }
        #pragma unroll
        for (int ks8 = 0; ks8 < 2; ks8++) {
            uint32_t af[4][4];
            uint32_t bf[4][2];
            #pragma unroll
            for (int mt = 0; mt < 4; mt++) {
                int m0 = wm * 64 + mt * 16 + l4;
                const uint32_t* pa = &As[st][m0 * LDP + ks8 * 8 + lk];
                af[mt][0] = pa[0];
                af[mt][1] = pa[8 * LDP];
                af[mt][2] = pa[4];
                af[mt][3] = pa[8 * LDP + 4];
            }
            #pragma unroll
            for (int nt = 0; nt < 4; nt++) {
                int n0 = wn * 32 + nt * 8 + l4;
                const uint32_t* pb = &Bs[st][n0 * LDP + ks8 * 8 + lk];
                bf[nt][0] = pb[0];
                bf[nt][1] = pb[4];
            }
            #pragma unroll
            for (int mt = 0; mt < 4; mt++)
                #pragma unroll
                for (int nt = 0; nt < 4; nt++)
                    mma_tf32(acc[mt][nt], af[mt], bf[nt]);
        }
        if (kc < NKC - 1) {
            int nst = (kc + 1) & 1;
            *(uint4*)&As[nst][sw]     = cvt4(pa0);
            *(uint4*)&As[nst][sw + 4] = cvt4(pa1);
            *(uint4*)&Bs[nst][sw]     = cvt4(pb0);
            *(uint4*)&Bs[nst][sw + 4] = cvt4(pb1);
        }
        __syncthreads();
    }

    // epilogue: bias + store (c0,c1 at row, c2,c3 at row+8; cols 2*(lane&3))
    #pragma unroll
    for (int mt = 0; mt < 4; mt++) {
        int r = row0 + wm * 64 + mt * 16 + l4;
        #pragma unroll
        for (int nt = 0; nt < 4; nt++) {
            int cl = wn * 32 + nt * 8 + (lk << 1);
            float bx = sbias[cl], by = sbias[cl + 1];
            float2 v0 = { acc[mt][nt][0] + bx, acc[mt][nt][1] + by };
            float2 v1 = { acc[mt][nt][2] + bx, acc[mt][nt][3] + by };
            *(float2*)&out[(size_t)r * C + col0 + cl]       = v0;
            *(float2*)&out[(size_t)(r + 8) * C + col0 + cl] = v1;
        }
    }
}

// ---------------------------------------------------------------- launch
extern "C" void kernel_launch(void* const* d_in, const int* in_sizes, int n_in,
                              void* d_out, int out_size)
{
    const float* x  = nullptr;
    const float* Wm = nullptr;
    const int*   ei = nullptr;
    const float* b1 = nullptr;
    const float* b2 = nullptr;

    for (int i = 0; i < n_in; i++) {
        int s = in_sizes[i];
        if (s == N_NODES * C)        x  = (const float*)d_in[i];
        else if (s == C * C)         Wm = (const float*)d_in[i];
        else if (s == 2 * 131072)    ei = (const int*)d_in[i];
        else if (s == C) {
            if (!b1) b1 = (const float*)d_in[i];
            else     b2 = (const float*)d_in[i];
        }
    }
    if (!b2) b2 = b1;
    float* out = (float*)d_out;
    int E = 131072;

    k_zero_bitmap<<<(N_NODES * NWORDS) / 256, 256>>>();
    k_set_edges<<<(E + 255) / 256, 256>>>(ei, E);
    k_deg<<<N_NODES / ROWS_PER_BLK, 256>>>();
    k_spmm<<<N_NODES / ROWS_PER_BLK, 256>>>(x);
    k_gemm_mma<<<dim3(N_NODES / GT_M, C / GT_N), 256>>>(Wm, b1, b2, out);
}

// round 7
// speedup vs baseline: 3.1370x; 1.5276x over previous
#include <cuda_runtime.h>
#include <cstdint>

#define N_NODES 8192
#define C 256
#define NWORDS 256   // 8192 bits / 32 per row
#define MAXDEG 128
#define ROWS_PER_BLK 8

// Scratch (device globals — no allocation allowed)
__device__ unsigned g_bitmap[N_NODES * NWORDS];   // 8 MiB adjacency bitmap
__device__ float    g_xs[N_NODES * C];            // dis[j] * x[j]
__device__ float    g_dis[N_NODES];
__device__ float    g_pre[N_NODES * C];           // norm @ x

// ---------------------------------------------------------------- K1: clear
__global__ void k_zero_bitmap() {
    int i = blockIdx.x * blockDim.x + threadIdx.x;
    g_bitmap[i] = 0u;
}

// ---------------------------------------------------------------- K2: edges
__global__ void k_set_edges(const int* __restrict__ ei, int E) {
    int e = blockIdx.x * blockDim.x + threadIdx.x;
    if (e < E) {
        int r = ei[e]     & (N_NODES - 1);
        int c = ei[E + e] & (N_NODES - 1);
        atomicOr(&g_bitmap[r * NWORDS + (c >> 5)], 1u << (c & 31));
    }
}

// ---------------------------------- K3: degree + prescale, warp-per-row
// dis_i = rsqrt(popcount(row)+1);  g_xs[i] = dis_i * x[i]
__global__ __launch_bounds__(256) void k_deg_scale(const float* __restrict__ x) {
    int warp = threadIdx.x >> 5;
    int lane = threadIdx.x & 31;
    int row  = blockIdx.x * ROWS_PER_BLK + warp;
    const unsigned* bm = &g_bitmap[row * NWORDS];
    uint4 a = *(const uint4*)&bm[lane * 8];
    uint4 b = *(const uint4*)&bm[lane * 8 + 4];
    int cnt = __popc(a.x) + __popc(a.y) + __popc(a.z) + __popc(a.w)
            + __popc(b.x) + __popc(b.y) + __popc(b.z) + __popc(b.w);
    #pragma unroll
    for (int d = 16; d; d >>= 1) cnt += __shfl_xor_sync(0xFFFFFFFFu, cnt, d);
    float dis = rsqrtf((float)(cnt + 1));
    if (lane == 0) g_dis[row] = dis;
    int ch = lane * 8;
    float4 v0 = *(const float4*)(x + row * C + ch);
    float4 v1 = *(const float4*)(x + row * C + ch + 4);
    v0.x *= dis; v0.y *= dis; v0.z *= dis; v0.w *= dis;
    v1.x *= dis; v1.y *= dis; v1.z *= dis; v1.w *= dis;
    *(float4*)(g_xs + row * C + ch)     = v0;
    *(float4*)(g_xs + row * C + ch + 4) = v1;
}

// --------------------------------------------------------------- K4: SpMM
// pre[i] = dis_i * ( xs_i + sum_{j in bits(i)} xs_j )   [xs prescaled]
__global__ __launch_bounds__(256) void k_spmm() {
    int warp = threadIdx.x >> 5;
    int lane = threadIdx.x & 31;
    int row  = blockIdx.x * ROWS_PER_BLK + warp;

    __shared__ int s_idx[ROWS_PER_BLK][MAXDEG];

    const unsigned* bm = &g_bitmap[row * NWORDS];
    unsigned w[8];
    *(uint4*)&w[0] = *(const uint4*)&bm[lane * 8];
    *(uint4*)&w[4] = *(const uint4*)&bm[lane * 8 + 4];
    int cnt = 0;
    #pragma unroll
    for (int q = 0; q < 8; q++) cnt += __popc(w[q]);
    int off = cnt;
    #pragma unroll
    for (int d = 1; d < 32; d <<= 1) {
        int v = __shfl_up_sync(0xFFFFFFFFu, off, d);
        if (lane >= d) off += v;
    }
    int total = __shfl_sync(0xFFFFFFFFu, off, 31);
    off -= cnt;
    if (total > MAXDEG) total = MAXDEG;
    int p = off;
    #pragma unroll
    for (int q = 0; q < 8; q++) {
        unsigned word = w[q];
        while (word) {
            int b = __ffs(word) - 1;
            word &= word - 1;
            if (p < MAXDEG) s_idx[warp][p] = ((lane * 8 + q) << 5) + b;
            p++;
        }
    }
    __syncwarp();

    const float* xs = g_xs;
    int ch = lane * 8;
    float4 a0 = *(const float4*)(xs + row * C + ch);      // eye term
    float4 a1 = *(const float4*)(xs + row * C + ch + 4);

    int k = 0;
    for (; k + 4 <= total; k += 4) {
        int4 j4 = *(const int4*)&s_idx[warp][k];
        const float* p0 = xs + j4.x * C + ch;
        const float* p1 = xs + j4.y * C + ch;
        const float* p2 = xs + j4.z * C + ch;
        const float* p3 = xs + j4.w * C + ch;
        float4 v00 = *(const float4*)p0, v01 = *(const float4*)(p0 + 4);
        float4 v10 = *(const float4*)p1, v11 = *(const float4*)(p1 + 4);
        float4 v20 = *(const float4*)p2, v21 = *(const float4*)(p2 + 4);
        float4 v30 = *(const float4*)p3, v31 = *(const float4*)(p3 + 4);
        a0.x += v00.x; a0.y += v00.y; a0.z += v00.z; a0.w += v00.w;
        a1.x += v01.x; a1.y += v01.y; a1.z += v01.z; a1.w += v01.w;
        a0.x += v10.x; a0.y += v10.y; a0.z += v10.z; a0.w += v10.w;
        a1.x += v11.x; a1.y += v11.y; a1.z += v11.z; a1.w += v11.w;
        a0.x += v20.x; a0.y += v20.y; a0.z += v20.z; a0.w += v20.w;
        a1.x += v21.x; a1.y += v21.y; a1.z += v21.z; a1.w += v21.w;
        a0.x += v30.x; a0.y += v30.y; a0.z += v30.z; a0.w += v30.w;
        a1.x += v31.x; a1.y += v31.y; a1.z += v31.z; a1.w += v31.w;
    }
    for (; k < total; k++) {
        int j = s_idx[warp][k];
        float4 v0 = *(const float4*)(xs + j * C + ch);
        float4 v1 = *(const float4*)(xs + j * C + ch + 4);
        a0.x += v0.x; a0.y += v0.y; a0.z += v0.z; a0.w += v0.w;
        a1.x += v1.x; a1.y += v1.y; a1.z += v1.z; a1.w += v1.w;
    }

    float disI = g_dis[row];
    a0.x *= disI; a0.y *= disI; a0.z *= disI; a0.w *= disI;
    a1.x *= disI; a1.y *= disI; a1.z *= disI; a1.w *= disI;
    *(float4*)(g_pre + row * C + ch)     = a0;
    *(float4*)(g_pre + row * C + ch + 4) = a1;
}

// ------------------------------------------- K5: tf32 mma.sync GEMM
// out[8192,256] = pre @ W^T + b1 + b2.
// CTA tile 128x128, 8 warps (2x4), warp tile 64x32, K chunk 16, dbl-buffered.
#define GT_M 128
#define GT_N 128
#define KSTEP 16
#define NKC (C / KSTEP)   // 16
#define LDP 20            // padded smem row stride (floats); conflict-free

__device__ __forceinline__ uint32_t f2tf32(float f) {
    uint32_t r;
    asm("cvt.rna.tf32.f32 %0, %1;" : "=r"(r) : "f"(f));
    return r;
}
__device__ __forceinline__ uint4 cvt4(float4 v) {
    uint4 r;
    r.x = f2tf32(v.x); r.y = f2tf32(v.y); r.z = f2tf32(v.z); r.w = f2tf32(v.w);
    return r;
}
__device__ __forceinline__ void mma_tf32(float* c, const uint32_t* a, const uint32_t* b) {
    asm volatile(
        "mma.sync.aligned.m16n8k8.row.col.f32.tf32.tf32.f32 "
        "{%0,%1,%2,%3}, {%4,%5,%6,%7}, {%8,%9}, {%0,%1,%2,%3};"
        : "+f"(c[0]), "+f"(c[1]), "+f"(c[2]), "+f"(c[3])
        : "r"(a[0]), "r"(a[1]), "r"(a[2]), "r"(a[3]), "r"(b[0]), "r"(b[1]));
}

__global__ __launch_bounds__(256) void k_gemm_mma(
    const float* __restrict__ Wm,
    const float* __restrict__ b1,
    const float* __restrict__ b2,
    float* __restrict__ out)
{
    __shared__ uint32_t As[2][GT_M * LDP];
    __shared__ uint32_t Bs[2][GT_N * LDP];
    __shared__ float sbias[GT_N];

    int tid  = threadIdx.x;
    int wid  = tid >> 5;
    int lane = tid & 31;
    int wm   = wid >> 2;           // 0..1
    int wn   = wid & 3;            // 0..3
    int row0 = blockIdx.x * GT_M;
    int col0 = blockIdx.y * GT_N;

    if (tid < GT_N) sbias[tid] = b1[col0 + tid] + b2[col0 + tid];

    int grow = tid >> 1;
    int gcol = (tid & 1) * 8;
    const float* agm = g_pre + (size_t)(row0 + grow) * C + gcol;
    const float* bgm = Wm    + (size_t)(col0 + grow) * C + gcol;
    uint32_t sw = grow * LDP + gcol;

    float4 pa0 = *(const float4*)(agm);
    float4 pa1 = *(const float4*)(agm + 4);
    float4 pb0 = *(const float4*)(bgm);
    float4 pb1 = *(const float4*)(bgm + 4);
    *(uint4*)&As[0][sw]     = cvt4(pa0);
    *(uint4*)&As[0][sw + 4] = cvt4(pa1);
    *(uint4*)&Bs[0][sw]     = cvt4(pb0);
    *(uint4*)&Bs[0][sw + 4] = cvt4(pb1);
    __syncthreads();

    float acc[4][4][4] = {};
    int l4  = lane >> 2;
    int lk  = lane & 3;

    for (int kc = 0; kc < NKC; kc++) {
        int st = kc & 1;
        if (kc < NKC - 1) {
            int ko = (kc + 1) * KSTEP;
            pa0 = *(const float4*)(agm + ko);
            pa1 = *(const float4*)(agm + ko + 4);
            pb0 = *(const float4*)(bgm + ko);
            pb1 = *(const float4*)(bgm + ko + 4);
        }
        #pragma unroll
        for (int ks8 = 0; ks8 < 2; ks8++) {
            uint32_t af[4][4];
            uint32_t bf[4][2];
            #pragma unroll
            for (int mt = 0; mt < 4; mt++) {
                int m0 = wm * 64 + mt * 16 + l4;
                const uint32_t* pa = &As[st][m0 * LDP + ks8 * 8 + lk];
                af[mt][0] = pa[0];
                af[mt][1] = pa[8 * LDP];
                af[mt][2] = pa[4];
                af[mt][3] = pa[8 * LDP + 4];
            }
            #pragma unroll
            for (int nt = 0; nt < 4; nt++) {
                int n0 = wn * 32 + nt * 8 + l4;
                const uint32_t* pb = &Bs[st][n0 * LDP + ks8 * 8 + lk];
                bf[nt][0] = pb[0];
                bf[nt][1] = pb[4];
            }
            #pragma unroll
            for (int mt = 0; mt < 4; mt++)
                #pragma unroll
                for (int nt = 0; nt < 4; nt++)
                    mma_tf32(acc[mt][nt], af[mt], bf[nt]);
        }
        if (kc < NKC - 1) {
            int nst = (kc + 1) & 1;
            *(uint4*)&As[nst][sw]     = cvt4(pa0);
            *(uint4*)&As[nst][sw + 4] = cvt4(pa1);
            *(uint4*)&Bs[nst][sw]     = cvt4(pb0);
            *(uint4*)&Bs[nst][sw + 4] = cvt4(pb1);
        }
        __syncthreads();
    }

    #pragma unroll
    for (int mt = 0; mt < 4; mt++) {
        int r = row0 + wm * 64 + mt * 16 + l4;
        #pragma unroll
        for (int nt = 0; nt < 4; nt++) {
            int cl = wn * 32 + nt * 8 + (lk << 1);
            float bx = sbias[cl], by = sbias[cl + 1];
            float2 v0 = { acc[mt][nt][0] + bx, acc[mt][nt][1] + by };
            float2 v1 = { acc[mt][nt][2] + bx, acc[mt][nt][3] + by };
            *(float2*)&out[(size_t)r * C + col0 + cl]       = v0;
            *(float2*)&out[(size_t)(r + 8) * C + col0 + cl] = v1;
        }
    }
}

// ---------------------------------------------------------------- launch
extern "C" void kernel_launch(void* const* d_in, const int* in_sizes, int n_in,
                              void* d_out, int out_size)
{
    const float* x  = nullptr;
    const float* Wm = nullptr;
    const int*   ei = nullptr;
    const float* b1 = nullptr;
    const float* b2 = nullptr;

    for (int i = 0; i < n_in; i++) {
        int s = in_sizes[i];
        if (s == N_NODES * C)        x  = (const float*)d_in[i];
        else if (s == C * C)         Wm = (const float*)d_in[i];
        else if (s == 2 * 131072)    ei = (const int*)d_in[i];
        else if (s == C) {
            if (!b1) b1 = (const float*)d_in[i];
            else     b2 = (const float*)d_in[i];
        }
    }
    if (!b2) b2 = b1;
    float* out = (float*)d_out;
    int E = 131072;

    k_zero_bitmap<<<(N_NODES * NWORDS) / 256, 256>>>();
    k_set_edges<<<(E + 255) / 256, 256>>>(ei, E);
    k_deg_scale<<<N_NODES / ROWS_PER_BLK, 256>>>(x);
    k_spmm<<<N_NODES / ROWS_PER_BLK, 256>>>();
    k_gemm_mma<<<dim3(N_NODES / GT_M, C / GT_N), 256>>>(Wm, b1, b2, out);
}

// round 9
// speedup vs baseline: 3.4451x; 1.0982x over previous
#include <cuda_runtime.h>
#include <cstdint>

#define N_NODES 8192
#define C 256
#define NWORDS 256   // 8192 bits / 32 per row
#define MAXDEG 128
#define ROWS_PER_BLK 8

// Scratch (device globals — no allocation allowed)
__device__ unsigned g_bitmap[N_NODES * NWORDS];   // 8 MiB adjacency bitmap
__device__ float    g_xs[N_NODES * C];            // dis[j] * x[j]
__device__ float    g_dis[N_NODES];
__device__ float    g_pre[N_NODES * C];           // norm @ x
__device__ int      g_adj[N_NODES * MAXDEG];      // 4 MiB neighbor lists
__device__ int      g_cnt[N_NODES];

// ---------------------------------------------------------------- K1: clear
__global__ void k_zero_bitmap() {
    int i = blockIdx.x * blockDim.x + threadIdx.x;
    ((uint4*)g_bitmap)[i] = make_uint4(0u, 0u, 0u, 0u);
}

// ---------------------------------------------------------------- K2: edges
__global__ void k_set_edges(const int* __restrict__ ei, int E) {
    int e = blockIdx.x * blockDim.x + threadIdx.x;
    if (e < E) {
        int r = ei[e]     & (N_NODES - 1);
        int c = ei[E + e] & (N_NODES - 1);
        atomicOr(&g_bitmap[r * NWORDS + (c >> 5)], 1u << (c & 31));
    }
}

// -------------------- K3: prep = degree + decode + prescale (warp-per-row)
// dis_i = rsqrt(popcount(row)+1);  g_xs[i] = dis_i * x[i];
// decode row bitmap -> g_adj[row][0..cnt), g_cnt[row]
__global__ __launch_bounds__(256) void k_prep(const float* __restrict__ x) {
    int warp = threadIdx.x >> 5;
    int lane = threadIdx.x & 31;
    int row  = blockIdx.x * ROWS_PER_BLK + warp;
    const unsigned* bm = &g_bitmap[row * NWORDS];
    unsigned w[8];
    *(uint4*)&w[0] = *(const uint4*)&bm[lane * 8];
    *(uint4*)&w[4] = *(const uint4*)&bm[lane * 8 + 4];
    int cnt = 0;
    #pragma unroll
    for (int q = 0; q < 8; q++) cnt += __popc(w[q]);
    // inclusive scan -> exclusive offset
    int off = cnt;
    #pragma unroll
    for (int d = 1; d < 32; d <<= 1) {
        int v = __shfl_up_sync(0xFFFFFFFFu, off, d);
        if (lane >= d) off += v;
    }
    int total = __shfl_sync(0xFFFFFFFFu, off, 31);
    off -= cnt;
    int tclamp = total > MAXDEG ? MAXDEG : total;
    if (lane == 0) g_cnt[row] = tclamp;
    int p = off;
    int* adj = &g_adj[row * MAXDEG];
    #pragma unroll
    for (int q = 0; q < 8; q++) {
        unsigned word = w[q];
        while (word) {
            int b = __ffs(word) - 1;
            word &= word - 1;
            if (p < MAXDEG) adj[p] = ((lane * 8 + q) << 5) + b;
            p++;
        }
    }
    float dis = rsqrtf((float)(total + 1));
    if (lane == 0) g_dis[row] = dis;
    int ch = lane * 8;
    float4 v0 = *(const float4*)(x + row * C + ch);
    float4 v1 = *(const float4*)(x + row * C + ch + 4);
    v0.x *= dis; v0.y *= dis; v0.z *= dis; v0.w *= dis;
    v1.x *= dis; v1.y *= dis; v1.z *= dis; v1.w *= dis;
    *(float4*)(g_xs + row * C + ch)     = v0;
    *(float4*)(g_xs + row * C + ch + 4) = v1;
}

// --------------------------------------------------------------- K4: SpMM
// warp = (row, channel-half). 4 rows x 2 halves per 256-thread block.
// Indices register-resident, broadcast via shfl. Each lane owns 4 channels.
__global__ __launch_bounds__(256) void k_spmm() {
    int warp = threadIdx.x >> 5;
    int lane = threadIdx.x & 31;
    int row  = blockIdx.x * 4 + (warp >> 1);
    int half = warp & 1;
    int ch   = half * 128 + lane * 4;

    int cnt = g_cnt[row];
    const int* adj = &g_adj[row * MAXDEG];
    int idx0 = 0, idx1 = 0, idx2 = 0, idx3 = 0;
    if (lane < cnt)      idx0 = adj[lane];
    if (32 + lane < cnt) idx1 = adj[32 + lane];
    if (64 + lane < cnt) idx2 = adj[64 + lane];
    if (96 + lane < cnt) idx3 = adj[96 + lane];

    const float* xs = g_xs;
    float4 a = *(const float4*)(xs + row * C + ch);   // eye term (prescaled)

    int seg = 0;
    #pragma unroll 1
    for (int base = 0; base < cnt; base += 32, seg++) {
        int reg = (seg == 0) ? idx0 : (seg == 1) ? idx1 : (seg == 2) ? idx2 : idx3;
        int n = cnt - base; if (n > 32) n = 32;
        int k = 0;
        for (; k + 4 <= n; k += 4) {
            int j0 = __shfl_sync(0xFFFFFFFFu, reg, k);
            int j1 = __shfl_sync(0xFFFFFFFFu, reg, k + 1);
            int j2 = __shfl_sync(0xFFFFFFFFu, reg, k + 2);
            int j3 = __shfl_sync(0xFFFFFFFFu, reg, k + 3);
            float4 v0 = *(const float4*)(xs + j0 * C + ch);
            float4 v1 = *(const float4*)(xs + j1 * C + ch);
            float4 v2 = *(const float4*)(xs + j2 * C + ch);
            float4 v3 = *(const float4*)(xs + j3 * C + ch);
            a.x += v0.x; a.y += v0.y; a.z += v0.z; a.w += v0.w;
            a.x += v1.x; a.y += v1.y; a.z += v1.z; a.w += v1.w;
            a.x += v2.x; a.y += v2.y; a.z += v2.z; a.w += v2.w;
            a.x += v3.x; a.y += v3.y; a.z += v3.z; a.w += v3.w;
        }
        for (; k < n; k++) {
            int j = __shfl_sync(0xFFFFFFFFu, reg, k);
            float4 v = *(const float4*)(xs + j * C + ch);
            a.x += v.x; a.y += v.y; a.z += v.z; a.w += v.w;
        }
    }

    float disI = g_dis[row];
    a.x *= disI; a.y *= disI; a.z *= disI; a.w *= disI;
    *(float4*)(g_pre + row * C + ch) = a;
}

// ------------------------------------------- K5: tf32 mma.sync GEMM
// out[8192,256] = pre @ W^T + b1 + b2.
// CTA tile 128x128, 8 warps (2x4), warp tile 64x32, K chunk 16, dbl-buffered.
#define GT_M 128
#define GT_N 128
#define KSTEP 16
#define NKC (C / KSTEP)   // 16
#define LDP 20            // padded smem row stride (floats); conflict-free

__device__ __forceinline__ uint32_t f2tf32(float f) {
    uint32_t r;
    asm("cvt.rna.tf32.f32 %0, %1;" : "=r"(r) : "f"(f));
    return r;
}
__device__ __forceinline__ uint4 cvt4(float4 v) {
    uint4 r;
    r.x = f2tf32(v.x); r.y = f2tf32(v.y); r.z = f2tf32(v.z); r.w = f2tf32(v.w);
    return r;
}
__device__ __forceinline__ void mma_tf32(float* c, const uint32_t* a, const uint32_t* b) {
    asm volatile(
        "mma.sync.aligned.m16n8k8.row.col.f32.tf32.tf32.f32 "
        "{%0,%1,%2,%3}, {%4,%5,%6,%7}, {%8,%9}, {%0,%1,%2,%3};"
        : "+f"(c[0]), "+f"(c[1]), "+f"(c[2]), "+f"(c[3])
        : "r"(a[0]), "r"(a[1]), "r"(a[2]), "r"(a[3]), "r"(b[0]), "r"(b[1]));
}

__global__ __launch_bounds__(256) void k_gemm_mma(
    const float* __restrict__ Wm,
    const float* __restrict__ b1,
    const float* __restrict__ b2,
    float* __restrict__ out)
{
    __shared__ uint32_t As[2][GT_M * LDP];
    __shared__ uint32_t Bs[2][GT_N * LDP];
    __shared__ float sbias[GT_N];

    int tid  = threadIdx.x;
    int wid  = tid >> 5;
    int lane = tid & 31;
    int wm   = wid >> 2;
    int wn   = wid & 3;
    int row0 = blockIdx.x * GT_M;
    int col0 = blockIdx.y * GT_N;

    if (tid < GT_N) sbias[tid] = b1[col0 + tid] + b2[col0 + tid];

    int grow = tid >> 1;
    int gcol = (tid & 1) * 8;
    const float* agm = g_pre + (size_t)(row0 + grow) * C + gcol;
    const float* bgm = Wm    + (size_t)(col0 + grow) * C + gcol;
    uint32_t sw = grow * LDP + gcol;

    float4 pa0 = *(const float4*)(agm);
    float4 pa1 = *(const float4*)(agm + 4);
    float4 pb0 = *(const float4*)(bgm);
    float4 pb1 = *(const float4*)(bgm + 4);
    *(uint4*)&As[0][sw]     = cvt4(pa0);
    *(uint4*)&As[0][sw + 4] = cvt4(pa1);
    *(uint4*)&Bs[0][sw]     = cvt4(pb0);
    *(uint4*)&Bs[0][sw + 4] = cvt4(pb1);
    __syncthreads();

    float acc[4][4][4] = {};
    int l4  = lane >> 2;
    int lk  = lane & 3;

    for (int kc = 0; kc < NKC; kc++) {
        int st = kc & 1;
        if (kc < NKC - 1) {
            int ko = (kc + 1) * KSTEP;
            pa0 = *(const float4*)(agm + ko);
            pa1 = *(const float4*)(agm + ko + 4);
            pb0 = *(const float4*)(bgm + ko);
            pb1 = *(const float4*)(bgm + ko + 4);
        }
        #pragma unroll
        for (int ks8 = 0; ks8 < 2; ks8++) {
            uint32_t af[4][4];
            uint32_t bf[4][2];
            #pragma unroll
            for (int mt = 0; mt < 4; mt++) {
                int m0 = wm * 64 + mt * 16 + l4;
                const uint32_t* pa = &As[st][m0 * LDP + ks8 * 8 + lk];
                af[mt][0] = pa[0];
                af[mt][1] = pa[8 * LDP];
                af[mt][2] = pa[4];
                af[mt][3] = pa[8 * LDP + 4];
            }
            #pragma unroll
            for (int nt = 0; nt < 4; nt++) {
                int n0 = wn * 32 + nt * 8 + l4;
                const uint32_t* pb = &Bs[st][n0 * LDP + ks8 * 8 + lk];
                bf[nt][0] = pb[0];
                bf[nt][1] = pb[4];
            }
            #pragma unroll
            for (int mt = 0; mt < 4; mt++)
                #pragma unroll
                for (int nt = 0; nt < 4; nt++)
                    mma_tf32(acc[mt][nt], af[mt], bf[nt]);
        }
        if (kc < NKC - 1) {
            int nst = (kc + 1) & 1;
            *(uint4*)&As[nst][sw]     = cvt4(pa0);
            *(uint4*)&As[nst][sw + 4] = cvt4(pa1);
            *(uint4*)&Bs[nst][sw]     = cvt4(pb0);
            *(uint4*)&Bs[nst][sw + 4] = cvt4(pb1);
        }
        __syncthreads();
    }

    #pragma unroll
    for (int mt = 0; mt < 4; mt++) {
        int r = row0 + wm * 64 + mt * 16 + l4;
        #pragma unroll
        for (int nt = 0; nt < 4; nt++) {
            int cl = wn * 32 + nt * 8 + (lk << 1);
            float bx = sbias[cl], by = sbias[cl + 1];
            float2 v0 = { acc[mt][nt][0] + bx, acc[mt][nt][1] + by };
            float2 v1 = { acc[mt][nt][2] + bx, acc[mt][nt][3] + by };
            *(float2*)&out[(size_t)r * C + col0 + cl]       = v0;
            *(float2*)&out[(size_t)(r + 8) * C + col0 + cl] = v1;
        }
    }
}

// ---------------------------------------------------------------- launch
extern "C" void kernel_launch(void* const* d_in, const int* in_sizes, int n_in,
                              void* d_out, int out_size)
{
    const float* x  = nullptr;
    const float* Wm = nullptr;
    const int*   ei = nullptr;
    const float* b1 = nullptr;
    const float* b2 = nullptr;

    for (int i = 0; i < n_in; i++) {
        int s = in_sizes[i];
        if (s == N_NODES * C)        x  = (const float*)d_in[i];
        else if (s == C * C)         Wm = (const float*)d_in[i];
        else if (s == 2 * 131072)    ei = (const int*)d_in[i];
        else if (s == C) {
            if (!b1) b1 = (const float*)d_in[i];
            else     b2 = (const float*)d_in[i];
        }
    }
    if (!b2) b2 = b1;
    float* out = (float*)d_out;
    int E = 131072;

    k_zero_bitmap<<<(N_NODES * NWORDS / 4) / 256, 256>>>();
    k_set_edges<<<(E + 255) / 256, 256>>>(ei, E);
    k_prep<<<N_NODES / ROWS_PER_BLK, 256>>>(x);
    k_spmm<<<N_NODES / 4, 256>>>();
    k_gemm_mma<<<dim3(N_NODES / GT_M, C / GT_N), 256>>>(Wm, b1, b2, out);
}

// round 10
// speedup vs baseline: 3.4664x; 1.0062x over previous
#include <cuda_runtime.h>
#include <cstdint>

#define N_NODES 8192
#define C 256
#define NWORDS 256   // 8192 bits / 32 per row
#define MAXDEG 128
#define ROWS_PER_BLK 8

// Scratch (device globals — no allocation allowed)
__device__ unsigned g_bitmap[N_NODES * NWORDS];   // 8 MiB adjacency bitmap (self-cleaning)
__device__ float    g_xs[N_NODES * C];            // dis[j] * x[j]
__device__ float    g_dis[N_NODES];
__device__ float    g_pre[N_NODES * C];           // norm @ x
__device__ int      g_adj[N_NODES * MAXDEG];      // 4 MiB neighbor lists
__device__ int      g_cnt[N_NODES];

// packed fp32x2 add/mul (Blackwell baseline PTX, sm_100+)
#define ADDX2(acc, v) asm("add.rn.f32x2 %0, %0, %1;" : "+l"(acc) : "l"(v))
#define MULX2(acc, v) asm("mul.rn.f32x2 %0, %0, %1;" : "+l"(acc) : "l"(v))
__device__ __forceinline__ unsigned long long d2l(double d) {
    return __double_as_longlong(d);
}

// ---------------------------------------------------------------- K2: edges
__global__ void k_set_edges(const int* __restrict__ ei, int E) {
    int e = blockIdx.x * blockDim.x + threadIdx.x;
    if (e < E) {
        int r = ei[e]     & (N_NODES - 1);
        int c = ei[E + e] & (N_NODES - 1);
        atomicOr(&g_bitmap[r * NWORDS + (c >> 5)], 1u << (c & 31));
    }
}

// ----- K3: prep = degree + decode + prescale + bitmap self-clear (warp/row)
__global__ __launch_bounds__(256) void k_prep(const float* __restrict__ x) {
    int warp = threadIdx.x >> 5;
    int lane = threadIdx.x & 31;
    int row  = blockIdx.x * ROWS_PER_BLK + warp;
    unsigned* bm = &g_bitmap[row * NWORDS];
    unsigned w[8];
    *(uint4*)&w[0] = *(const uint4*)&bm[lane * 8];
    *(uint4*)&w[4] = *(const uint4*)&bm[lane * 8 + 4];
    // self-clear for next graph replay (set_edges of next launch re-populates)
    uint4 z = make_uint4(0u, 0u, 0u, 0u);
    *(uint4*)&bm[lane * 8]     = z;
    *(uint4*)&bm[lane * 8 + 4] = z;

    int cnt = 0;
    #pragma unroll
    for (int q = 0; q < 8; q++) cnt += __popc(w[q]);
    int off = cnt;
    #pragma unroll
    for (int d = 1; d < 32; d <<= 1) {
        int v = __shfl_up_sync(0xFFFFFFFFu, off, d);
        if (lane >= d) off += v;
    }
    int total = __shfl_sync(0xFFFFFFFFu, off, 31);
    off -= cnt;
    int tclamp = total > MAXDEG ? MAXDEG : total;
    if (lane == 0) g_cnt[row] = tclamp;
    int p = off;
    int* adj = &g_adj[row * MAXDEG];
    #pragma unroll
    for (int q = 0; q < 8; q++) {
        unsigned word = w[q];
        while (word) {
            int b = __ffs(word) - 1;
            word &= word - 1;
            if (p < MAXDEG) adj[p] = ((lane * 8 + q) << 5) + b;
            p++;
        }
    }
    float dis = rsqrtf((float)(total + 1));
    if (lane == 0) g_dis[row] = dis;
    int ch = lane * 8;
    float4 v0 = *(const float4*)(x + row * C + ch);
    float4 v1 = *(const float4*)(x + row * C + ch + 4);
    v0.x *= dis; v0.y *= dis; v0.z *= dis; v0.w *= dis;
    v1.x *= dis; v1.y *= dis; v1.z *= dis; v1.w *= dis;
    *(float4*)(g_xs + row * C + ch)     = v0;
    *(float4*)(g_xs + row * C + ch + 4) = v1;
}

// --------------------------------------------------------------- K4: SpMM
// warp = (row, 128-ch half); lane owns 4 channels (one 16B vector).
// Indices: broadcast LDG.128 from g_adj. Accumulate: packed f32x2 adds on
// double2-loaded neighbor vectors (no pack movs). MLP=8.
__global__ __launch_bounds__(256) void k_spmm() {
    int warp = threadIdx.x >> 5;
    int lane = threadIdx.x & 31;
    int row  = blockIdx.x * 4 + (warp >> 1);
    int ch   = (warp & 1) * 128 + lane * 4;

    int cnt = g_cnt[row];
    const int* adj = &g_adj[row * MAXDEG];
    const float* xs = g_xs;

    double2 e = *(const double2*)(xs + row * C + ch);   // eye term (prescaled)
    unsigned long long acc0 = d2l(e.x);
    unsigned long long acc1 = d2l(e.y);

    int k = 0;
    for (; k + 8 <= cnt; k += 8) {
        int4 ja = *(const int4*)&adj[k];
        int4 jb = *(const int4*)&adj[k + 4];
        double2 v0 = *(const double2*)(xs + ja.x * C + ch);
        double2 v1 = *(const double2*)(xs + ja.y * C + ch);
        double2 v2 = *(const double2*)(xs + ja.z * C + ch);
        double2 v3 = *(const double2*)(xs + ja.w * C + ch);
        double2 v4 = *(const double2*)(xs + jb.x * C + ch);
        double2 v5 = *(const double2*)(xs + jb.y * C + ch);
        double2 v6 = *(const double2*)(xs + jb.z * C + ch);
        double2 v7 = *(const double2*)(xs + jb.w * C + ch);
        ADDX2(acc0, d2l(v0.x)); ADDX2(acc1, d2l(v0.y));
        ADDX2(acc0, d2l(v1.x)); ADDX2(acc1, d2l(v1.y));
        ADDX2(acc0, d2l(v2.x)); ADDX2(acc1, d2l(v2.y));
        ADDX2(acc0, d2l(v3.x)); ADDX2(acc1, d2l(v3.y));
        ADDX2(acc0, d2l(v4.x)); ADDX2(acc1, d2l(v4.y));
        ADDX2(acc0, d2l(v5.x)); ADDX2(acc1, d2l(v5.y));
        ADDX2(acc0, d2l(v6.x)); ADDX2(acc1, d2l(v6.y));
        ADDX2(acc0, d2l(v7.x)); ADDX2(acc1, d2l(v7.y));
    }
    for (; k + 4 <= cnt; k += 4) {
        int4 ja = *(const int4*)&adj[k];
        double2 v0 = *(const double2*)(xs + ja.x * C + ch);
        double2 v1 = *(const double2*)(xs + ja.y * C + ch);
        double2 v2 = *(const double2*)(xs + ja.z * C + ch);
        double2 v3 = *(const double2*)(xs + ja.w * C + ch);
        ADDX2(acc0, d2l(v0.x)); ADDX2(acc1, d2l(v0.y));
        ADDX2(acc0, d2l(v1.x)); ADDX2(acc1, d2l(v1.y));
        ADDX2(acc0, d2l(v2.x)); ADDX2(acc1, d2l(v2.y));
        ADDX2(acc0, d2l(v3.x)); ADDX2(acc1, d2l(v3.y));
    }
    for (; k < cnt; k++) {
        int j = adj[k];
        double2 v = *(const double2*)(xs + j * C + ch);
        ADDX2(acc0, d2l(v.x)); ADDX2(acc1, d2l(v.y));
    }

    float disI = g_dis[row];
    unsigned long long dp;
    asm("mov.b64 %0, {%1, %1};" : "=l"(dp) : "r"(__float_as_uint(disI)));
    MULX2(acc0, dp);
    MULX2(acc1, dp);
    double2 o;
    o.x = __longlong_as_double(acc0);
    o.y = __longlong_as_double(acc1);
    *(double2*)(g_pre + row * C + ch) = o;
}

// ------------------------------------------- K5: tf32 mma.sync GEMM
// out[8192,256] = pre @ W^T + b1 + b2.
// CTA tile 128x128, 8 warps (2x4), warp tile 64x32, K chunk 16, dbl-buffered.
#define GT_M 128
#define GT_N 128
#define KSTEP 16
#define NKC (C / KSTEP)   // 16
#define LDP 20            // padded smem row stride (floats); conflict-free

__device__ __forceinline__ uint32_t f2tf32(float f) {
    uint32_t r;
    asm("cvt.rna.tf32.f32 %0, %1;" : "=r"(r) : "f"(f));
    return r;
}
__device__ __forceinline__ uint4 cvt4(float4 v) {
    uint4 r;
    r.x = f2tf32(v.x); r.y = f2tf32(v.y); r.z = f2tf32(v.z); r.w = f2tf32(v.w);
    return r;
}
__device__ __forceinline__ void mma_tf32(float* c, const uint32_t* a, const uint32_t* b) {
    asm volatile(
        "mma.sync.aligned.m16n8k8.row.col.f32.tf32.tf32.f32 "
        "{%0,%1,%2,%3}, {%4,%5,%6,%7}, {%8,%9}, {%0,%1,%2,%3};"
        : "+f"(c[0]), "+f"(c[1]), "+f"(c[2]), "+f"(c[3])
        : "r"(a[0]), "r"(a[1]), "r"(a[2]), "r"(a[3]), "r"(b[0]), "r"(b[1]));
}

__global__ __launch_bounds__(256) void k_gemm_mma(
    const float* __restrict__ Wm,
    const float* __restrict__ b1,
    const float* __restrict__ b2,
    float* __restrict__ out)
{
    __shared__ uint32_t As[2][GT_M * LDP];
    __shared__ uint32_t Bs[2][GT_N * LDP];
    __shared__ float sbias[GT_N];

    int tid  = threadIdx.x;
    int wid  = tid >> 5;
    int lane = tid & 31;
    int wm   = wid >> 2;
    int wn   = wid & 3;
    int row0 = blockIdx.x * GT_M;
    int col0 = blockIdx.y * GT_N;

    if (tid < GT_N) sbias[tid] = b1[col0 + tid] + b2[col0 + tid];

    int grow = tid >> 1;
    int gcol = (tid & 1) * 8;
    const float* agm = g_pre + (size_t)(row0 + grow) * C + gcol;
    const float* bgm = Wm    + (size_t)(col0 + grow) * C + gcol;
    uint32_t sw = grow * LDP + gcol;

    float4 pa0 = *(const float4*)(agm);
    float4 pa1 = *(const float4*)(agm + 4);
    float4 pb0 = *(const float4*)(bgm);
    float4 pb1 = *(const float4*)(bgm + 4);
    *(uint4*)&As[0][sw]     = cvt4(pa0);
    *(uint4*)&As[0][sw + 4] = cvt4(pa1);
    *(uint4*)&Bs[0][sw]     = cvt4(pb0);
    *(uint4*)&Bs[0][sw + 4] = cvt4(pb1);
    __syncthreads();

    float acc[4][4][4] = {};
    int l4  = lane >> 2;
    int lk  = lane & 3;

    for (int kc = 0; kc < NKC; kc++) {
        int st = kc & 1;
        if (kc < NKC - 1) {
            int ko = (kc + 1) * KSTEP;
            pa0 = *(const float4*)(agm + ko);
            pa1 = *(const float4*)(agm + ko + 4);
            pb0 = *(const float4*)(bgm + ko);
            pb1 = *(const float4*)(bgm + ko + 4);
        }
        #pragma unroll
        for (int ks8 = 0; ks8 < 2; ks8++) {
            uint32_t af[4][4];
            uint32_t bf[4][2];
            #pragma unroll
            for (int mt = 0; mt < 4; mt++) {
                int m0 = wm * 64 + mt * 16 + l4;
                const uint32_t* pa = &As[st][m0 * LDP + ks8 * 8 + lk];
                af[mt][0] = pa[0];
                af[mt][1] = pa[8 * LDP];
                af[mt][2] = pa[4];
                af[mt][3] = pa[8 * LDP + 4];
            }
            #pragma unroll
            for (int nt = 0; nt < 4; nt++) {
                int n0 = wn * 32 + nt * 8 + l4;
                const uint32_t* pb = &Bs[st][n0 * LDP + ks8 * 8 + lk];
                bf[nt][0] = pb[0];
                bf[nt][1] = pb[4];
            }
            #pragma unroll
            for (int mt = 0; mt < 4; mt++)
                #pragma unroll
                for (int nt = 0; nt < 4; nt++)
                    mma_tf32(acc[mt][nt], af[mt], bf[nt]);
        }
        if (kc < NKC - 1) {
            int nst = (kc + 1) & 1;
            *(uint4*)&As[nst][sw]     = cvt4(pa0);
            *(uint4*)&As[nst][sw + 4] = cvt4(pa1);
            *(uint4*)&Bs[nst][sw]     = cvt4(pb0);
            *(uint4*)&Bs[nst][sw + 4] = cvt4(pb1);
        }
        __syncthreads();
    }

    #pragma unroll
    for (int mt = 0; mt < 4; mt++) {
        int r = row0 + wm * 64 + mt * 16 + l4;
        #pragma unroll
        for (int nt = 0; nt < 4; nt++) {
            int cl = wn * 32 + nt * 8 + (lk << 1);
            float bx = sbias[cl], by = sbias[cl + 1];
            float2 v0 = { acc[mt][nt][0] + bx, acc[mt][nt][1] + by };
            float2 v1 = { acc[mt][nt][2] + bx, acc[mt][nt][3] + by };
            *(float2*)&out[(size_t)r * C + col0 + cl]       = v0;
            *(float2*)&out[(size_t)(r + 8) * C + col0 + cl] = v1;
        }
    }
}

// ---------------------------------------------------------------- launch
extern "C" void kernel_launch(void* const* d_in, const int* in_sizes, int n_in,
                              void* d_out, int out_size)
{
    const float* x  = nullptr;
    const float* Wm = nullptr;
    const int*   ei = nullptr;
    const float* b1 = nullptr;
    const float* b2 = nullptr;

    for (int i = 0; i < n_in; i++) {
        int s = in_sizes[i];
        if (s == N_NODES * C)        x  = (const float*)d_in[i];
        else if (s == C * C)         Wm = (const float*)d_in[i];
        else if (s == 2 * 131072)    ei = (const int*)d_in[i];
        else if (s == C) {
            if (!b1) b1 = (const float*)d_in[i];
            else     b2 = (const float*)d_in[i];
        }
    }
    if (!b2) b2 = b1;
    float* out = (float*)d_out;
    int E = 131072;

    k_set_edges<<<(E + 255) / 256, 256>>>(ei, E);
    k_prep<<<N_NODES / ROWS_PER_BLK, 256>>>(x);
    k_spmm<<<N_NODES / 4, 256>>>();
    k_gemm_mma<<<dim3(N_NODES / GT_M, C / GT_N), 256>>>(Wm, b1, b2, out);
}